// round 1
// baseline (speedup 1.0000x reference)
#include <cuda_runtime.h>

// Problem constants (fixed shapes per reference)
#define B_SZ 1024
#define V_SZ 1024
#define L_SZ 16
#define W_SZ 8192
#define NUM_LEAVES (2 * V_SZ)              // 2048
#define N_INTERNAL (L_SZ * W_SZ)           // 131072
#define TOTAL_NODES (NUM_LEAVES + N_INTERNAL)

// Scratch (static __device__ globals — allocation-free per harness rules)
__device__ int   g_mark[N_INTERNAL];           // 512 KB: dedupe flags for internal nodes
__device__ int   g_mcnt[L_SZ];                 // marked count per layer
__device__ int   g_mlist[L_SZ][W_SZ];          // marked node ids per layer (global node index)
__device__ int4  g_work[L_SZ][W_SZ];           // (node, li, ri, op) work items per layer
__device__ float g_vals[(size_t)N_INTERNAL * B_SZ];  // 512 MB: only marked rows are touched

// ---------------------------------------------------------------------------
// 1) Init: clear marks + counts, seed root into layer L-1's frontier.
// ---------------------------------------------------------------------------
__global__ void init_kernel() {
    int i = blockIdx.x * blockDim.x + threadIdx.x;
    if (i < N_INTERNAL) g_mark[i] = (i == N_INTERNAL - 1) ? 1 : 0;
    if (i < L_SZ)       g_mcnt[i] = (i == L_SZ - 1) ? 1 : 0;
    if (i == 0)         g_mlist[L_SZ - 1][0] = TOTAL_NODES - 1;
}

// ---------------------------------------------------------------------------
// 2) Backward reachability (single block). Layers processed descending: a
//    node in layer j can only be marked by layers > j, so its frontier list
//    is final when we reach it. Emits compact forward work items.
// ---------------------------------------------------------------------------
__global__ void mark_kernel(const int* __restrict__ left,
                            const int* __restrict__ right,
                            const int* __restrict__ op) {
    const int tid = threadIdx.x;
    for (int l = L_SZ - 1; l >= 0; --l) {
        const int n     = g_mcnt[l];
        const int avail = NUM_LEAVES + l * W_SZ;
        for (int s = tid; s < n; s += blockDim.x) {
            const int node = g_mlist[l][s];
            const int w    = node - avail;                // local index in layer l
            const int li   = left[l * W_SZ + w]  % avail;
            const int ri   = right[l * W_SZ + w] % avail;
            const int opv  = op[l * W_SZ + w];
            g_work[l][s] = make_int4(node, li, ri, opv);
            #pragma unroll
            for (int k = 0; k < 2; ++k) {
                const int c = (k == 0) ? li : ri;
                if (c >= NUM_LEAVES) {                    // internal child → mark + enqueue
                    if (atomicExch(&g_mark[c - NUM_LEAVES], 1) == 0) {
                        const int j   = (c - NUM_LEAVES) / W_SZ;
                        const int pos = atomicAdd(&g_mcnt[j], 1);
                        g_mlist[j][pos] = c;
                    }
                }
            }
        }
        __syncthreads();   // layer l fully processed before moving to l-1
    }
}

// ---------------------------------------------------------------------------
// 3) Forward, one layer: grid-strides over the compact work list. Each block
//    handles one node = one 1024-float row; 256 threads x float4.
//    Leaves are read virtually from x (value = x or 1-x). Root row is also
//    written to d_out.
// ---------------------------------------------------------------------------
__device__ __forceinline__ float4 getval4(const float* __restrict__ x, int node, int b) {
    float4 r;
    if (node < V_SZ) {                        // leaf: x[:, node]  (strided by V)
        r.x = x[(size_t)(b + 0) * V_SZ + node];
        r.y = x[(size_t)(b + 1) * V_SZ + node];
        r.z = x[(size_t)(b + 2) * V_SZ + node];
        r.w = x[(size_t)(b + 3) * V_SZ + node];
    } else if (node < NUM_LEAVES) {           // leaf: 1 - x[:, node-V]
        const int v = node - V_SZ;
        r.x = 1.0f - x[(size_t)(b + 0) * V_SZ + v];
        r.y = 1.0f - x[(size_t)(b + 1) * V_SZ + v];
        r.z = 1.0f - x[(size_t)(b + 2) * V_SZ + v];
        r.w = 1.0f - x[(size_t)(b + 3) * V_SZ + v];
    } else {                                  // internal: coalesced row read
        r = *reinterpret_cast<const float4*>(
                &g_vals[(size_t)(node - NUM_LEAVES) * B_SZ + b]);
    }
    return r;
}

__global__ void forward_kernel(const float* __restrict__ x, float* __restrict__ out, int l) {
    const int n = g_mcnt[l];
    const int b = threadIdx.x * 4;            // 256 threads cover B=1024
    for (int s = blockIdx.x; s < n; s += gridDim.x) {
        const int4 wk = g_work[l][s];
        const float4 a = getval4(x, wk.y, b);
        const float4 c = getval4(x, wk.z, b);
        float4 r;
        if (wk.w == 1) { r.x = a.x + c.x; r.y = a.y + c.y; r.z = a.z + c.z; r.w = a.w + c.w; }
        else           { r.x = a.x * c.x; r.y = a.y * c.y; r.z = a.z * c.z; r.w = a.w * c.w; }
        *reinterpret_cast<float4*>(&g_vals[(size_t)(wk.x - NUM_LEAVES) * B_SZ + b]) = r;
        if (wk.x == TOTAL_NODES - 1)
            *reinterpret_cast<float4*>(&out[b]) = r;      // root → output
    }
}

// ---------------------------------------------------------------------------
// kernel_launch: inputs per metadata order: x [B*V f32], left_idx [L*W i32],
// right_idx [L*W i32], op [L*W i32]. Output: float[B].
// ---------------------------------------------------------------------------
extern "C" void kernel_launch(void* const* d_in, const int* in_sizes, int n_in,
                              void* d_out, int out_size) {
    const float* x     = (const float*)d_in[0];
    const int*   left  = (const int*)d_in[1];
    const int*   right = (const int*)d_in[2];
    const int*   op    = (const int*)d_in[3];
    float*       out   = (float*)d_out;

    (void)in_sizes; (void)n_in; (void)out_size;

    init_kernel<<<(N_INTERNAL + 255) / 256, 256>>>();
    mark_kernel<<<1, 1024>>>(left, right, op);
    for (int l = 0; l < L_SZ; ++l)
        forward_kernel<<<128, 256>>>(x, out, l);
}

// round 2
// speedup vs baseline: 2.7433x; 2.7433x over previous
#include <cuda_runtime.h>

// Problem constants (fixed shapes per reference)
#define B_SZ 1024
#define V_SZ 1024
#define L_SZ 16
#define W_SZ 8192
#define NUM_LEAVES (2 * V_SZ)              // 2048
#define N_INTERNAL (L_SZ * W_SZ)           // 131072
#define TOTAL_NODES (NUM_LEAVES + N_INTERNAL)

// Persistent scratch (__device__ globals; zero-initialized at module load).
// g_mark is left all-zero at kernel exit (self-cleaning) so every graph
// replay sees identical initial state -> deterministic.
__device__ int   g_mark[N_INTERNAL];                    // dedupe flags
__device__ int   g_mlist[L_SZ][W_SZ];                   // frontier node ids per layer
__device__ int4  g_work[L_SZ][W_SZ];                    // (node, li, ri, op)
__device__ float g_vals[(size_t)N_INTERNAL * B_SZ];     // only marked rows touched

// Leaf/internal value for batch element b.
__device__ __forceinline__ float getval(const float* __restrict__ x, int node, int b) {
    if (node < V_SZ)        return x[(size_t)b * V_SZ + node];           // x[:, node]
    if (node < NUM_LEAVES)  return 1.0f - x[(size_t)b * V_SZ + (node - V_SZ)];
    return g_vals[(size_t)(node - NUM_LEAVES) * B_SZ + b];               // internal row
}

// ---------------------------------------------------------------------------
// Single fused kernel, one block of 1024 threads (= B).
// Phase 1: backward reachability (layers descending) -> compact work lists.
// Phase 2: forward eval (layers ascending), one node per block-iteration,
//          thread tid handles batch element tid (coalesced row I/O).
// Phase 3: self-clean the mark flags via the frontier lists.
// ---------------------------------------------------------------------------
__global__ void __launch_bounds__(1024, 1)
fused_kernel(const float* __restrict__ x,
             const int* __restrict__ left,
             const int* __restrict__ right,
             const int* __restrict__ op,
             float* __restrict__ out) {
    __shared__ int s_cnt[L_SZ];
    const int tid = threadIdx.x;

    // Seed: root node into layer L-1's frontier.
    if (tid < L_SZ) s_cnt[tid] = (tid == L_SZ - 1) ? 1 : 0;
    if (tid == 0) {
        g_mlist[L_SZ - 1][0] = TOTAL_NODES - 1;
        g_mark[N_INTERNAL - 1] = 1;
    }
    __syncthreads();

    // ---- Phase 1: mark (descending). A node in layer j is only enqueued by
    // layers > j, so its list is final when we reach it.
    for (int l = L_SZ - 1; l >= 0; --l) {
        const int n     = s_cnt[l];
        const int avail = NUM_LEAVES + l * W_SZ;
        for (int s = tid; s < n; s += blockDim.x) {
            const int node = g_mlist[l][s];
            const int w    = node - avail;
            const int li   = left[l * W_SZ + w]  % avail;
            const int ri   = right[l * W_SZ + w] % avail;
            const int opv  = op[l * W_SZ + w];
            g_work[l][s] = make_int4(node, li, ri, opv);
            #pragma unroll
            for (int k = 0; k < 2; ++k) {
                const int c = (k == 0) ? li : ri;
                if (c >= NUM_LEAVES) {
                    if (atomicExch(&g_mark[c - NUM_LEAVES], 1) == 0) {
                        const int j   = (c - NUM_LEAVES) / W_SZ;
                        const int pos = atomicAdd(&s_cnt[j], 1);
                        g_mlist[j][pos] = c;
                    }
                }
            }
        }
        __syncthreads();
    }

    // ---- Phase 2: forward (ascending). tid == batch index (B == 1024).
    for (int l = 0; l < L_SZ; ++l) {
        const int n = s_cnt[l];
        for (int s = 0; s < n; ++s) {
            const int4  wk = g_work[l][s];
            const float a  = getval(x, wk.y, tid);
            const float c  = getval(x, wk.z, tid);
            const float r  = (wk.w == 1) ? (a + c) : (a * c);
            g_vals[(size_t)(wk.x - NUM_LEAVES) * B_SZ + tid] = r;
            if (wk.x == TOTAL_NODES - 1) out[tid] = r;    // root -> output
        }
        __syncthreads();   // layer l values visible before layer l+1 reads
    }

    // ---- Phase 3: self-clean marks (restores all-zero invariant).
    for (int l = 0; l < L_SZ; ++l) {
        const int n = s_cnt[l];
        for (int s = tid; s < n; s += blockDim.x)
            g_mark[g_mlist[l][s] - NUM_LEAVES] = 0;
    }
}

// ---------------------------------------------------------------------------
// kernel_launch: inputs per metadata order: x [B*V f32], left_idx [L*W i32],
// right_idx [L*W i32], op [L*W i32]. Output: float[B].
// ---------------------------------------------------------------------------
extern "C" void kernel_launch(void* const* d_in, const int* in_sizes, int n_in,
                              void* d_out, int out_size) {
    const float* x     = (const float*)d_in[0];
    const int*   left  = (const int*)d_in[1];
    const int*   right = (const int*)d_in[2];
    const int*   op    = (const int*)d_in[3];
    float*       out   = (float*)d_out;
    (void)in_sizes; (void)n_in; (void)out_size;

    fused_kernel<<<1, 1024>>>(x, left, right, op, out);
}